// round 1
// baseline (speedup 1.0000x reference)
#include <cuda_runtime.h>
#include <math.h>

// ---------------- Problem constants ----------------
#define BCH   8
#define NS    2097152
#define LBLK  512                 // samples per block
#define KPC   (NS/LBLK)           // 4096 blocks per channel
#define NBLK  (BCH*KPC)           // 32768 blocks total
#define TPB   128                 // threads per CTA (phase kernels)
#define BLKS_PER_CTA (2*TPB)      // 256 blocks per CTA (f32x2 pairing)
#define NCTA  (NBLK/BLKS_PER_CTA) // 128 CTAs
#define CHUNK 32                  // samples staged per chunk
#define NCHUNK (LBLK/CHUNK)       // 16 chunks
#define RPAD  257                 // column stride (odd -> conflict-free)
#define DTR   8                   // scan truncation depth (M^8 = A^4096 ~ 1e-14)
#define PI_D  3.14159265358979323846
#define SR_D  44100.0

// ---------------- Device scratch (no cudaMalloc allowed) ----------------
__device__ float g_coef[5][5];        // b0,b1,b2,a1,a2 per biquad (normalized)
__device__ float g_Mpow[DTR][100];    // M^0 .. M^(DTR-1), M = A^LBLK (10x10)
__device__ float g_f[NBLK][10];       // zero-state final state per block
__device__ float g_s0[NBLK][10];      // reconstructed initial state per block

typedef unsigned long long ull;

// ---------------- f32x2 packed math (sm_103a) ----------------
__device__ __forceinline__ ull pk2(float lo, float hi) {
    ull r; asm("mov.b64 %0, {%1,%2};" : "=l"(r) : "f"(lo), "f"(hi)); return r;
}
__device__ __forceinline__ void upk2(ull v, float& lo, float& hi) {
    asm("mov.b64 {%0,%1}, %2;" : "=f"(lo), "=f"(hi) : "l"(v));
}
__device__ __forceinline__ ull fma2(ull a, ull b, ull c) {
    ull d; asm("fma.rn.f32x2 %0, %1, %2, %3;" : "=l"(d) : "l"(a), "l"(b), "l"(c)); return d;
}
__device__ __forceinline__ ull mul2(ull a, ull b) {
    ull d; asm("mul.rn.f32x2 %0, %1, %2;" : "=l"(d) : "l"(a), "l"(b)); return d;
}

// ---------------- Setup: coeffs + A + M powers ----------------
__global__ void eq_setup_kernel(const float* __restrict__ eq) {
    __shared__ double sc[5][5];
    __shared__ double Abuf[100], Ma[100], Mb[100];
    int t = threadIdx.x;

    if (t == 0) {
        for (int i = 0; i < 5; i++) {
            double g = (double)eq[i*3+0], fc = (double)eq[i*3+1], q = (double)eq[i*3+2];
            double Av = pow(10.0, g / 40.0);
            double w0 = 2.0 * PI_D * fc / SR_D;
            double al = sin(w0) / (2.0 * q);
            double c  = cos(w0);
            double b0, b1, b2, a0, a1, a2;
            if (i == 0 || i == 4) {           // shelf: i==0 low (sgn=-1), i==4 high (sgn=+1)
                double sgn = (i == 4) ? 1.0 : -1.0;
                double sA = sqrt(Av);
                b0 = Av * ((Av + 1.0) + sgn * (Av - 1.0) * c + 2.0 * sA * al);
                b1 = -2.0 * sgn * Av * ((Av - 1.0) + sgn * (Av + 1.0) * c);
                b2 = Av * ((Av + 1.0) + sgn * (Av - 1.0) * c - 2.0 * sA * al);
                a0 = (Av + 1.0) - sgn * (Av - 1.0) * c + 2.0 * sA * al;
                a1 = 2.0 * sgn * ((Av - 1.0) - sgn * (Av + 1.0) * c);
                a2 = (Av + 1.0) - sgn * (Av - 1.0) * c - 2.0 * sA * al;
            } else {                           // peaking
                b0 = 1.0 + al * Av; b1 = -2.0 * c; b2 = 1.0 - al * Av;
                a0 = 1.0 + al / Av; a1 = -2.0 * c; a2 = 1.0 - al / Av;
            }
            sc[i][0] = b0 / a0; sc[i][1] = b1 / a0; sc[i][2] = b2 / a0;
            sc[i][3] = a1 / a0; sc[i][4] = a2 / a0;
            for (int j = 0; j < 5; j++) g_coef[i][j] = (float)sc[i][j];
        }
        // Build homogeneous transition A (state = s1_1,s2_1,...,s1_5,s2_5).
        // DF2T per biquad:  y = b0*u + s1;  s1' = b1*u - a1*y + s2;  s2' = b2*u - a2*y
        // Homogeneous input functional: U_1 = 0; U_{i+1} = b0_i*U_i + e_{s1_i}
        double U[10]; for (int j = 0; j < 10; j++) U[j] = 0.0;
        for (int j = 0; j < 100; j++) Abuf[j] = 0.0;
        for (int i = 0; i < 5; i++) {
            double b0 = sc[i][0], b1 = sc[i][1], b2 = sc[i][2], a1 = sc[i][3], a2 = sc[i][4];
            double p1 = b1 - a1 * b0, p2 = b2 - a2 * b0;
            for (int j = 0; j < 10; j++) {
                Abuf[(2*i)*10 + j]   += p1 * U[j];
                Abuf[(2*i+1)*10 + j] += p2 * U[j];
            }
            Abuf[(2*i)*10 + 2*i]     += -a1;
            Abuf[(2*i)*10 + 2*i + 1] += 1.0;
            Abuf[(2*i+1)*10 + 2*i]   += -a2;
            for (int j = 0; j < 10; j++) U[j] *= b0;
            U[2*i] += 1.0;
        }
    }
    __syncthreads();

    if (t < 100) Ma[t] = Abuf[t];
    __syncthreads();

    // M = A^512 via 9 squarings (parallel over 100 elements)
    double* src = Ma; double* dst = Mb;
    for (int s = 0; s < 9; s++) {
        if (t < 100) {
            int r = t / 10, c = t % 10;
            double acc = 0.0;
            for (int k = 0; k < 10; k++) acc += src[r*10 + k] * src[k*10 + c];
            dst[t] = acc;
        }
        __syncthreads();
        double* tmp = src; src = dst; dst = tmp;
    }
    // src = M. Store M^0 (I), M^1, then chain P = P*M for d=2..DTR-1 (Abuf reused as P).
    if (t < 100) {
        int r = t / 10, c = t % 10;
        g_Mpow[0][t] = (r == c) ? 1.0f : 0.0f;
        g_Mpow[1][t] = (float)src[t];
        Abuf[t] = src[t];
    }
    __syncthreads();
    double* P = Abuf; double* Q = dst;
    for (int d = 2; d < DTR; d++) {
        if (t < 100) {
            int r = t / 10, c = t % 10;
            double acc = 0.0;
            for (int k = 0; k < 10; k++) acc += P[r*10 + k] * src[k*10 + c];
            Q[t] = acc;
        }
        __syncthreads();
        if (t < 100) g_Mpow[d][t] = (float)Q[t];
        __syncthreads();
        double* tmp = P; P = Q; Q = tmp;
    }
}

// ---------------- Shared helpers for the phase kernels ----------------
struct Coefs { ull cb0[5], cb1[5], cb2[5], na1[5], na2[5]; };

__device__ __forceinline__ void load_coefs(Coefs& C) {
#pragma unroll
    for (int i = 0; i < 5; i++) {
        float b0 = g_coef[i][0], b1 = g_coef[i][1], b2 = g_coef[i][2];
        float a1 = g_coef[i][3], a2 = g_coef[i][4];
        C.cb0[i] = pk2(b0, b0); C.cb1[i] = pk2(b1, b1); C.cb2[i] = pk2(b2, b2);
        C.na1[i] = pk2(-a1, -a1); C.na2[i] = pk2(-a2, -a2);
    }
}

// one sample through the 5-biquad cascade for two packed blocks
__device__ __forceinline__ ull cascade_step(const Coefs& C, ull u, ull s1[5], ull s2[5]) {
#pragma unroll
    for (int i = 0; i < 5; i++) {
        ull y  = fma2(C.cb0[i], u, s1[i]);
        s1[i]  = fma2(C.cb1[i], u, fma2(C.na1[i], y, s2[i]));
        s2[i]  = fma2(C.cb2[i], u, mul2(C.na2[i], y));
        u = y;
    }
    return u;
}

// ---------------- Phase 1: zero-state recurrence, emit final states ----------------
__global__ void __launch_bounds__(TPB, 1) eq_phase1_kernel(const float* __restrict__ x) {
    extern __shared__ float sx[];                 // [CHUNK][RPAD] column-major tile
    const int t = threadIdx.x;
    const long base = (long)blockIdx.x * (BLKS_PER_CTA * LBLK);

    Coefs C; load_coefs(C);
    ull s1[5] = {0,0,0,0,0}, s2[5] = {0,0,0,0,0};

    float4 pf[16];
#pragma unroll
    for (int j = 0; j < 16; j++) {
        int idx = j * TPB + t; int br = idx >> 3, cg = idx & 7;
        pf[j] = *(const float4*)(x + base + (long)br * LBLK + cg * 4);
    }

    for (int q = 0; q < NCHUNK; q++) {
#pragma unroll
        for (int j = 0; j < 16; j++) {
            int idx = j * TPB + t; int br = idx >> 3, cg = idx & 7;
            float4 v = pf[j];
            sx[(cg*4+0)*RPAD + br] = v.x;
            sx[(cg*4+1)*RPAD + br] = v.y;
            sx[(cg*4+2)*RPAD + br] = v.z;
            sx[(cg*4+3)*RPAD + br] = v.w;
        }
        __syncthreads();
        if (q + 1 < NCHUNK) {
#pragma unroll
            for (int j = 0; j < 16; j++) {
                int idx = j * TPB + t; int br = idx >> 3, cg = idx & 7;
                pf[j] = *(const float4*)(x + base + (long)br * LBLK + (q+1) * CHUNK + cg * 4);
            }
        }
#pragma unroll 4
        for (int c = 0; c < CHUNK; c++) {
            float xa = sx[c*RPAD + t];
            float xb = sx[c*RPAD + TPB + t];
            (void)cascade_step(C, pk2(xa, xb), s1, s2);
        }
        __syncthreads();
    }

    const int b0i = blockIdx.x * BLKS_PER_CTA + t;
    const int b1i = b0i + TPB;
#pragma unroll
    for (int i = 0; i < 5; i++) {
        float lo, hi;
        upk2(s1[i], lo, hi); g_f[b0i][2*i]   = lo; g_f[b1i][2*i]   = hi;
        upk2(s2[i], lo, hi); g_f[b0i][2*i+1] = lo; g_f[b1i][2*i+1] = hi;
    }
}

// ---------------- Phase 2: truncated state scan  s0[k] = sum_{d=1..DTR} M^{d-1} f[k-d] ----------------
__global__ void eq_scan_kernel() {
    const int k = blockIdx.x * blockDim.x + threadIdx.x;
    if (k >= NBLK) return;
    const int kl = k & (KPC - 1);   // block index within channel
    float s[10];
#pragma unroll
    for (int j = 0; j < 10; j++) s[j] = 0.0f;
    for (int d = 1; d <= DTR; d++) {
        if (kl - d < 0) break;
        const float* fv = g_f[k - d];
        const float* Mp = g_Mpow[d - 1];
        float fr[10];
#pragma unroll
        for (int j = 0; j < 10; j++) fr[j] = fv[j];
#pragma unroll
        for (int r = 0; r < 10; r++) {
            float acc = s[r];
#pragma unroll
            for (int c = 0; c < 10; c++) acc = fmaf(Mp[r*10 + c], fr[c], acc);
            s[r] = acc;
        }
    }
#pragma unroll
    for (int j = 0; j < 10; j++) g_s0[k][j] = s[j];
}

// ---------------- Phase 3: exact re-run with reconstructed initial states, emit y ----------------
__global__ void __launch_bounds__(TPB, 1) eq_phase3_kernel(const float* __restrict__ x,
                                                           float* __restrict__ y) {
    extern __shared__ float sm[];
    float* sx = sm;                      // [CHUNK][RPAD] input tile
    float* sy = sm + CHUNK * RPAD;       // [CHUNK][RPAD] output tile
    const int t = threadIdx.x;
    const long base = (long)blockIdx.x * (BLKS_PER_CTA * LBLK);

    Coefs C; load_coefs(C);
    const int b0i = blockIdx.x * BLKS_PER_CTA + t;
    const int b1i = b0i + TPB;
    ull s1[5], s2[5];
#pragma unroll
    for (int i = 0; i < 5; i++) {
        s1[i] = pk2(g_s0[b0i][2*i],   g_s0[b1i][2*i]);
        s2[i] = pk2(g_s0[b0i][2*i+1], g_s0[b1i][2*i+1]);
    }

    float4 pf[16];
#pragma unroll
    for (int j = 0; j < 16; j++) {
        int idx = j * TPB + t; int br = idx >> 3, cg = idx & 7;
        pf[j] = *(const float4*)(x + base + (long)br * LBLK + cg * 4);
    }

    for (int q = 0; q < NCHUNK; q++) {
#pragma unroll
        for (int j = 0; j < 16; j++) {
            int idx = j * TPB + t; int br = idx >> 3, cg = idx & 7;
            float4 v = pf[j];
            sx[(cg*4+0)*RPAD + br] = v.x;
            sx[(cg*4+1)*RPAD + br] = v.y;
            sx[(cg*4+2)*RPAD + br] = v.z;
            sx[(cg*4+3)*RPAD + br] = v.w;
        }
        __syncthreads();
        if (q + 1 < NCHUNK) {
#pragma unroll
            for (int j = 0; j < 16; j++) {
                int idx = j * TPB + t; int br = idx >> 3, cg = idx & 7;
                pf[j] = *(const float4*)(x + base + (long)br * LBLK + (q+1) * CHUNK + cg * 4);
            }
        }
#pragma unroll 4
        for (int c = 0; c < CHUNK; c++) {
            float xa = sx[c*RPAD + t];
            float xb = sx[c*RPAD + TPB + t];
            ull u = cascade_step(C, pk2(xa, xb), s1, s2);
            float ya, yb; upk2(u, ya, yb);
            sy[c*RPAD + t]       = ya;
            sy[c*RPAD + TPB + t] = yb;
        }
        __syncthreads();
        // cooperative coalesced write of the output tile
#pragma unroll
        for (int j = 0; j < 16; j++) {
            int idx = j * TPB + t; int br = idx >> 3, cg = idx & 7;
            float4 v;
            v.x = sy[(cg*4+0)*RPAD + br];
            v.y = sy[(cg*4+1)*RPAD + br];
            v.z = sy[(cg*4+2)*RPAD + br];
            v.w = sy[(cg*4+3)*RPAD + br];
            *(float4*)(y + base + (long)br * LBLK + q * CHUNK + cg * 4) = v;
        }
        __syncthreads();
    }
}

// ---------------- Launch ----------------
extern "C" void kernel_launch(void* const* d_in, const int* in_sizes, int n_in,
                              void* d_out, int out_size) {
    (void)in_sizes; (void)n_in; (void)out_size;
    const float* x  = (const float*)d_in[0];
    const float* eq = (const float*)d_in[1];
    float* y = (float*)d_out;

    const int smem1 = CHUNK * RPAD * (int)sizeof(float);        // 32896 B
    const int smem3 = 2 * CHUNK * RPAD * (int)sizeof(float);    // 65792 B
    cudaFuncSetAttribute((const void*)eq_phase1_kernel,
                         cudaFuncAttributeMaxDynamicSharedMemorySize, smem1);
    cudaFuncSetAttribute((const void*)eq_phase3_kernel,
                         cudaFuncAttributeMaxDynamicSharedMemorySize, smem3);

    eq_setup_kernel<<<1, 128>>>(eq);
    eq_phase1_kernel<<<NCTA, TPB, smem1>>>(x);
    eq_scan_kernel<<<NBLK / 256, 256>>>();
    eq_phase3_kernel<<<NCTA, TPB, smem3>>>(x, y);
}

// round 2
// speedup vs baseline: 1.3353x; 1.3353x over previous
#include <cuda_runtime.h>
#include <math.h>

// ---------------- Problem constants ----------------
#define BCH   8
#define NS    2097152
#define LBLK  128                 // samples per block
#define KPC   (NS/LBLK)           // 16384 blocks per channel
#define NBLK  (BCH*KPC)           // 131072 blocks total
#define TPB   128                 // threads per CTA (phase kernels)
#define BLKS_PER_CTA (2*TPB)      // 256 blocks per CTA (f32x2 pairing)
#define NCTA  (NBLK/BLKS_PER_CTA) // 512 CTAs
#define CHUNK 32                  // samples staged per chunk
#define NCHUNK (LBLK/CHUNK)       // 4 chunks
#define RPAD  257                 // column stride (conflict-free)
#define DTR   16                  // scan depth: decay^16 ~ 4e-7
#define SBLK  256                 // blocks per scan CTA
#define PI_D  3.14159265358979323846
#define SR_D  44100.0

// ---------------- Device scratch ----------------
__device__ float g_coef[5][5];        // b0, p1, p2, -a1, -a2 per biquad
__device__ float g_M[100];            // M = A^LBLK (10x10)
__device__ float g_f[NBLK][10];       // zero-state final state per block
__device__ float g_s0[NBLK][10];      // reconstructed initial state per block

typedef unsigned long long ull;

// ---------------- f32x2 packed math (sm_103a) ----------------
__device__ __forceinline__ ull pk2(float lo, float hi) {
    ull r; asm("mov.b64 %0, {%1,%2};" : "=l"(r) : "f"(lo), "f"(hi)); return r;
}
__device__ __forceinline__ void upk2(ull v, float& lo, float& hi) {
    asm("mov.b64 {%0,%1}, %2;" : "=f"(lo), "=f"(hi) : "l"(v));
}
__device__ __forceinline__ ull fma2(ull a, ull b, ull c) {
    ull d; asm("fma.rn.f32x2 %0, %1, %2, %3;" : "=l"(d) : "l"(a), "l"(b), "l"(c)); return d;
}
__device__ __forceinline__ ull mul2(ull a, ull b) {
    ull d; asm("mul.rn.f32x2 %0, %1, %2;" : "=l"(d) : "l"(a), "l"(b)); return d;
}

// ---------------- Setup: coeffs + A + M = A^128 ----------------
__global__ void eq_setup_kernel(const float* __restrict__ eq) {
    __shared__ double sc[5][5];
    __shared__ double Abuf[100], Ma[100], Mb[100];
    int t = threadIdx.x;

    if (t < 5) {
        int i = t;
        double g = (double)eq[i*3+0], fc = (double)eq[i*3+1], q = (double)eq[i*3+2];
        double Av = pow(10.0, g / 40.0);
        double w0 = 2.0 * PI_D * fc / SR_D;
        double al = sin(w0) / (2.0 * q);
        double c  = cos(w0);
        double b0, b1, b2, a0, a1, a2;
        if (i == 0 || i == 4) {
            double sgn = (i == 4) ? 1.0 : -1.0;
            double sA = sqrt(Av);
            b0 = Av * ((Av + 1.0) + sgn * (Av - 1.0) * c + 2.0 * sA * al);
            b1 = -2.0 * sgn * Av * ((Av - 1.0) + sgn * (Av + 1.0) * c);
            b2 = Av * ((Av + 1.0) + sgn * (Av - 1.0) * c - 2.0 * sA * al);
            a0 = (Av + 1.0) - sgn * (Av - 1.0) * c + 2.0 * sA * al;
            a1 = 2.0 * sgn * ((Av - 1.0) - sgn * (Av + 1.0) * c);
            a2 = (Av + 1.0) - sgn * (Av - 1.0) * c - 2.0 * sA * al;
        } else {
            b0 = 1.0 + al * Av; b1 = -2.0 * c; b2 = 1.0 - al * Av;
            a0 = 1.0 + al / Av; a1 = -2.0 * c; a2 = 1.0 - al / Av;
        }
        double b0n = b0/a0, b1n = b1/a0, b2n = b2/a0, a1n = a1/a0, a2n = a2/a0;
        sc[i][0] = b0n; sc[i][1] = b1n; sc[i][2] = b2n; sc[i][3] = a1n; sc[i][4] = a2n;
        g_coef[i][0] = (float)b0n;
        g_coef[i][1] = (float)(b1n - a1n * b0n);   // p1
        g_coef[i][2] = (float)(b2n - a2n * b0n);   // p2
        g_coef[i][3] = (float)(-a1n);
        g_coef[i][4] = (float)(-a2n);
    }
    __syncthreads();

    if (t == 0) {
        // Homogeneous transition A for DF2T cascade state (s1_1,s2_1,...,s1_5,s2_5)
        double U[10]; for (int j = 0; j < 10; j++) U[j] = 0.0;
        for (int j = 0; j < 100; j++) Abuf[j] = 0.0;
        for (int i = 0; i < 5; i++) {
            double b0 = sc[i][0], b1 = sc[i][1], b2 = sc[i][2], a1 = sc[i][3], a2 = sc[i][4];
            double p1 = b1 - a1 * b0, p2 = b2 - a2 * b0;
            for (int j = 0; j < 10; j++) {
                Abuf[(2*i)*10 + j]   += p1 * U[j];
                Abuf[(2*i+1)*10 + j] += p2 * U[j];
            }
            Abuf[(2*i)*10 + 2*i]     += -a1;
            Abuf[(2*i)*10 + 2*i + 1] += 1.0;
            Abuf[(2*i+1)*10 + 2*i]   += -a2;
            for (int j = 0; j < 10; j++) U[j] *= b0;
            U[2*i] += 1.0;
        }
    }
    __syncthreads();

    if (t < 100) Ma[t] = Abuf[t];
    __syncthreads();

    // M = A^128 via 7 squarings
    double* src = Ma; double* dst = Mb;
    for (int s = 0; s < 7; s++) {
        if (t < 100) {
            int r = t / 10, c = t % 10;
            double acc = 0.0;
            for (int k = 0; k < 10; k++) acc += src[r*10 + k] * src[k*10 + c];
            dst[t] = acc;
        }
        __syncthreads();
        double* tmp = src; src = dst; dst = tmp;
    }
    if (t < 100) g_M[t] = (float)src[t];
}

// ---------------- Cascade (state-space form, 4-cycle recurrence chain) ----------------
struct Coefs { ull b0[5], p1[5], p2[5], na1[5], na2[5]; };

__device__ __forceinline__ void load_coefs(Coefs& C) {
#pragma unroll
    for (int i = 0; i < 5; i++) {
        float b0 = g_coef[i][0], p1 = g_coef[i][1], p2 = g_coef[i][2];
        float na1 = g_coef[i][3], na2 = g_coef[i][4];
        C.b0[i] = pk2(b0, b0); C.p1[i] = pk2(p1, p1); C.p2[i] = pk2(p2, p2);
        C.na1[i] = pk2(na1, na1); C.na2[i] = pk2(na2, na2);
    }
}

__device__ __forceinline__ ull cascade_step(const Coefs& C, ull u, ull s1[5], ull s2[5]) {
#pragma unroll
    for (int i = 0; i < 5; i++) {
        ull y   = fma2(C.b0[i], u, s1[i]);          // output (off state chain)
        ull tt  = fma2(C.p1[i], u, s2[i]);          // off-chain
        ull w   = mul2(C.p2[i], u);                 // off-chain
        ull s1n = fma2(C.na1[i], s1[i], tt);        // chain: s1 -> s1' (4 cyc)
        s2[i]   = fma2(C.na2[i], s1[i], w);
        s1[i]   = s1n;
        u = y;
    }
    return u;
}

// ---------------- Phase 1: zero-state recurrence, emit final states ----------------
__global__ void __launch_bounds__(TPB, 3) eq_phase1_kernel(const float* __restrict__ x) {
    extern __shared__ float sx[];                 // [CHUNK][RPAD]
    const int t = threadIdx.x;
    const long base = (long)blockIdx.x * (BLKS_PER_CTA * LBLK);

    Coefs C; load_coefs(C);
    ull s1[5] = {0,0,0,0,0}, s2[5] = {0,0,0,0,0};

    float4 pf[16];
#pragma unroll
    for (int j = 0; j < 16; j++) {
        int idx = j * TPB + t; int br = idx >> 3, cg = idx & 7;
        pf[j] = *(const float4*)(x + base + (long)br * LBLK + cg * 4);
    }

    for (int q = 0; q < NCHUNK; q++) {
#pragma unroll
        for (int j = 0; j < 16; j++) {
            int idx = j * TPB + t; int br = idx >> 3, cg = idx & 7;
            float4 v = pf[j];
            sx[(cg*4+0)*RPAD + br] = v.x;
            sx[(cg*4+1)*RPAD + br] = v.y;
            sx[(cg*4+2)*RPAD + br] = v.z;
            sx[(cg*4+3)*RPAD + br] = v.w;
        }
        __syncthreads();
        if (q + 1 < NCHUNK) {
#pragma unroll
            for (int j = 0; j < 16; j++) {
                int idx = j * TPB + t; int br = idx >> 3, cg = idx & 7;
                pf[j] = *(const float4*)(x + base + (long)br * LBLK + (q+1) * CHUNK + cg * 4);
            }
        }
#pragma unroll 4
        for (int c = 0; c < CHUNK; c++) {
            float xa = sx[c*RPAD + t];
            float xb = sx[c*RPAD + TPB + t];
            (void)cascade_step(C, pk2(xa, xb), s1, s2);
        }
        __syncthreads();
    }

    const int b0i = blockIdx.x * BLKS_PER_CTA + t;
    const int b1i = b0i + TPB;
#pragma unroll
    for (int i = 0; i < 5; i++) {
        float lo, hi;
        upk2(s1[i], lo, hi); g_f[b0i][2*i]   = lo; g_f[b1i][2*i]   = hi;
        upk2(s2[i], lo, hi); g_f[b0i][2*i+1] = lo; g_f[b1i][2*i+1] = hi;
    }
}

// ---------------- Phase 2: Horner scan  s0[k] = sum_{d=1..DTR} M^{d-1} f[k-d] ----------------
__global__ void __launch_bounds__(128, 3) eq_scan_kernel() {
    __shared__ float sf[SBLK + DTR][10];    // f tile
    __shared__ float sM[100];
    const int t = threadIdx.x;
    const int K0 = blockIdx.x * SBLK;
    const int ch0 = K0 & ~(KPC - 1);        // channel start (CTA never straddles channels)

    if (t < 100) sM[t] = g_M[t];
    for (int i = t; i < (SBLK + DTR) * 10; i += 128) {
        int row = i / 10, j = i % 10;
        int k = K0 - DTR + row;
        sf[row][j] = (k >= ch0) ? g_f[k][j] : 0.0f;
    }
    __syncthreads();

    float M[100];
#pragma unroll
    for (int i = 0; i < 100; i++) M[i] = sM[i];

    // thread handles blocks K0+t (lo) and K0+128+t (hi); tile row for k-d is t+DTR-d (+128)
    ull s[10];
#pragma unroll
    for (int j = 0; j < 10; j++) s[j] = pk2(sf[t][j], sf[t + 128][j]);   // f[k-DTR]

#pragma unroll 1
    for (int d = DTR - 1; d >= 1; d--) {
        int r0 = t + (DTR - d);
        ull a[10];
#pragma unroll
        for (int j = 0; j < 10; j++) a[j] = pk2(sf[r0][j], sf[r0 + 128][j]);
#pragma unroll
        for (int r = 0; r < 10; r++) {
            ull acc = a[r];
#pragma unroll
            for (int c = 0; c < 10; c++) {
                ull m2 = pk2(M[r*10 + c], M[r*10 + c]);
                acc = fma2(m2, s[c], acc);
            }
            a[r] = acc;
        }
#pragma unroll
        for (int j = 0; j < 10; j++) s[j] = a[j];
    }

    const int k0 = K0 + t, k1 = k0 + 128;
#pragma unroll
    for (int j = 0; j < 10; j++) {
        float lo, hi; upk2(s[j], lo, hi);
        g_s0[k0][j] = lo; g_s0[k1][j] = hi;
    }
}

// ---------------- Phase 3: exact re-run with reconstructed initial states ----------------
__global__ void __launch_bounds__(TPB, 3) eq_phase3_kernel(const float* __restrict__ x,
                                                           float* __restrict__ y) {
    extern __shared__ float sm[];
    float* sx = sm;                      // [CHUNK][RPAD] input tile
    float* sy = sm + CHUNK * RPAD;       // [CHUNK][RPAD] output tile
    const int t = threadIdx.x;
    const long base = (long)blockIdx.x * (BLKS_PER_CTA * LBLK);

    Coefs C; load_coefs(C);
    const int b0i = blockIdx.x * BLKS_PER_CTA + t;
    const int b1i = b0i + TPB;
    ull s1[5], s2[5];
#pragma unroll
    for (int i = 0; i < 5; i++) {
        s1[i] = pk2(g_s0[b0i][2*i],   g_s0[b1i][2*i]);
        s2[i] = pk2(g_s0[b0i][2*i+1], g_s0[b1i][2*i+1]);
    }

    float4 pf[16];
#pragma unroll
    for (int j = 0; j < 16; j++) {
        int idx = j * TPB + t; int br = idx >> 3, cg = idx & 7;
        pf[j] = *(const float4*)(x + base + (long)br * LBLK + cg * 4);
    }

    for (int q = 0; q < NCHUNK; q++) {
#pragma unroll
        for (int j = 0; j < 16; j++) {
            int idx = j * TPB + t; int br = idx >> 3, cg = idx & 7;
            float4 v = pf[j];
            sx[(cg*4+0)*RPAD + br] = v.x;
            sx[(cg*4+1)*RPAD + br] = v.y;
            sx[(cg*4+2)*RPAD + br] = v.z;
            sx[(cg*4+3)*RPAD + br] = v.w;
        }
        __syncthreads();
        if (q + 1 < NCHUNK) {
#pragma unroll
            for (int j = 0; j < 16; j++) {
                int idx = j * TPB + t; int br = idx >> 3, cg = idx & 7;
                pf[j] = *(const float4*)(x + base + (long)br * LBLK + (q+1) * CHUNK + cg * 4);
            }
        }
#pragma unroll 4
        for (int c = 0; c < CHUNK; c++) {
            float xa = sx[c*RPAD + t];
            float xb = sx[c*RPAD + TPB + t];
            ull u = cascade_step(C, pk2(xa, xb), s1, s2);
            float ya, yb; upk2(u, ya, yb);
            sy[c*RPAD + t]       = ya;
            sy[c*RPAD + TPB + t] = yb;
        }
        __syncthreads();
#pragma unroll
        for (int j = 0; j < 16; j++) {
            int idx = j * TPB + t; int br = idx >> 3, cg = idx & 7;
            float4 v;
            v.x = sy[(cg*4+0)*RPAD + br];
            v.y = sy[(cg*4+1)*RPAD + br];
            v.z = sy[(cg*4+2)*RPAD + br];
            v.w = sy[(cg*4+3)*RPAD + br];
            *(float4*)(y + base + (long)br * LBLK + q * CHUNK + cg * 4) = v;
        }
        __syncthreads();
    }
}

// ---------------- Launch ----------------
extern "C" void kernel_launch(void* const* d_in, const int* in_sizes, int n_in,
                              void* d_out, int out_size) {
    (void)in_sizes; (void)n_in; (void)out_size;
    const float* x  = (const float*)d_in[0];
    const float* eq = (const float*)d_in[1];
    float* y = (float*)d_out;

    const int smem1 = CHUNK * RPAD * (int)sizeof(float);        // 32896 B
    const int smem3 = 2 * CHUNK * RPAD * (int)sizeof(float);    // 65792 B
    cudaFuncSetAttribute((const void*)eq_phase1_kernel,
                         cudaFuncAttributeMaxDynamicSharedMemorySize, smem1);
    cudaFuncSetAttribute((const void*)eq_phase3_kernel,
                         cudaFuncAttributeMaxDynamicSharedMemorySize, smem3);

    eq_setup_kernel<<<1, 128>>>(eq);
    eq_phase1_kernel<<<NCTA, TPB, smem1>>>(x);
    eq_scan_kernel<<<NBLK / SBLK, 128>>>();
    eq_phase3_kernel<<<NCTA, TPB, smem3>>>(x, y);
}